// round 1
// baseline (speedup 1.0000x reference)
#include <cuda_runtime.h>
#include <math.h>

// ---------------------------------------------------------------------------
// Scratch (allocation-free rule: __device__ globals)
// ---------------------------------------------------------------------------
__device__ float g_Q [(size_t)4096 * 1024];
__device__ float g_K [(size_t)4096 * 1024];
__device__ float g_V [(size_t)4096 * 1024];
__device__ float g_Y [(size_t)4096 * 1024];
__device__ float g_FF[(size_t)4096 * 4096];

__device__ __forceinline__ float gelu_f(float v) {
    return 0.5f * v * (1.0f + erff(v * 0.70710678118654752f));
}

// ---------------------------------------------------------------------------
// SGEMM: C[M,N] = A[M,K] @ B[K,N] + bias (+ GELU | + residual)
// 128x128 block tile, BK=8, 256 threads, 8x8 per thread (4x4 quads),
// double-buffered SMEM.
// EPI: 0 = bias, 1 = bias+gelu, 2 = bias+residual
// ---------------------------------------------------------------------------
template<int EPI>
__global__ __launch_bounds__(256, 2)
void sgemm_kernel(const float* __restrict__ A, const float* __restrict__ B,
                  const float* __restrict__ bias, const float* __restrict__ R,
                  float* __restrict__ C, int M, int N, int K)
{
    __shared__ __align__(16) float As[2][8][132];   // padded: conflict-free transpose
    __shared__ __align__(16) float Bs[2][8][128];

    const int t  = threadIdx.x;
    const int tx = t & 15;
    const int ty = t >> 4;
    const int m0 = blockIdx.y * 128;
    const int n0 = blockIdx.x * 128;

    const int ar = t >> 1;          // 0..127 (A tile row)
    const int ac = (t & 1) * 4;     // 0 or 4 (A tile k-col)
    const int br = t >> 5;          // 0..7   (B tile k-row)
    const int bc = (t & 31) * 4;    // 0..124 (B tile col)

    const float* Ap = A + (size_t)(m0 + ar) * K + ac;
    const float* Bp = B + (size_t)br * N + n0 + bc;

    // prologue: tile 0
    {
        float4 av = *(const float4*)Ap;
        float4 bv = *(const float4*)Bp;
        As[0][ac + 0][ar] = av.x; As[0][ac + 1][ar] = av.y;
        As[0][ac + 2][ar] = av.z; As[0][ac + 3][ar] = av.w;
        *(float4*)&Bs[0][br][bc] = bv;
    }
    __syncthreads();

    float acc[8][8];
    #pragma unroll
    for (int i = 0; i < 8; ++i)
        #pragma unroll
        for (int j = 0; j < 8; ++j) acc[i][j] = 0.0f;

    const int KT = K >> 3;
    int buf = 0;
    for (int kt = 0; kt < KT; ++kt) {
        float4 an, bn;
        const bool more = (kt + 1 < KT);
        if (more) {
            an = *(const float4*)(Ap + (size_t)(kt + 1) * 8);
            bn = *(const float4*)(Bp + (size_t)(kt + 1) * 8 * N);
        }
        #pragma unroll
        for (int k = 0; k < 8; ++k) {
            float4 a0 = *(const float4*)&As[buf][k][ty * 4];
            float4 a1 = *(const float4*)&As[buf][k][ty * 4 + 64];
            float4 b0 = *(const float4*)&Bs[buf][k][tx * 4];
            float4 b1 = *(const float4*)&Bs[buf][k][tx * 4 + 64];
            float a[8] = {a0.x, a0.y, a0.z, a0.w, a1.x, a1.y, a1.z, a1.w};
            float b[8] = {b0.x, b0.y, b0.z, b0.w, b1.x, b1.y, b1.z, b1.w};
            #pragma unroll
            for (int i = 0; i < 8; ++i)
                #pragma unroll
                for (int j = 0; j < 8; ++j)
                    acc[i][j] = fmaf(a[i], b[j], acc[i][j]);
        }
        if (more) {
            const int nb = buf ^ 1;
            As[nb][ac + 0][ar] = an.x; As[nb][ac + 1][ar] = an.y;
            As[nb][ac + 2][ar] = an.z; As[nb][ac + 3][ar] = an.w;
            *(float4*)&Bs[nb][br][bc] = bn;
        }
        __syncthreads();
        buf ^= 1;
    }

    // epilogue
    #pragma unroll
    for (int iq = 0; iq < 2; ++iq)
    #pragma unroll
    for (int i = 0; i < 4; ++i) {
        const int row = m0 + ty * 4 + iq * 64 + i;
        #pragma unroll
        for (int jq = 0; jq < 2; ++jq) {
            const int col = n0 + tx * 4 + jq * 64;
            float4 bb = *(const float4*)&bias[col];
            float4 r;
            r.x = acc[iq * 4 + i][jq * 4 + 0] + bb.x;
            r.y = acc[iq * 4 + i][jq * 4 + 1] + bb.y;
            r.z = acc[iq * 4 + i][jq * 4 + 2] + bb.z;
            r.w = acc[iq * 4 + i][jq * 4 + 3] + bb.w;
            if (EPI == 1) {
                r.x = gelu_f(r.x); r.y = gelu_f(r.y);
                r.z = gelu_f(r.z); r.w = gelu_f(r.w);
            }
            if (EPI == 2) {
                float4 rv = *(const float4*)&R[(size_t)row * N + col];
                r.x += rv.x; r.y += rv.y; r.z += rv.z; r.w += rv.w;
            }
            *(float4*)&C[(size_t)row * N + col] = r;
        }
    }
}

// ---------------------------------------------------------------------------
// Flash attention, fp32. One CTA = (64 queries) x (one batch-head).
// Tiles of 64 KV, online softmax. Q pre-scaled by 1/sqrt(64).
// Dynamic SMEM: Qs[64][64] (transposed), KP[64][68] (K^T, then P^T), Vs[64][64],
// mk[64] mask ints.
// ---------------------------------------------------------------------------
__global__ __launch_bounds__(256, 1)
void attn_kernel(const float* __restrict__ Q, const float* __restrict__ K,
                 const float* __restrict__ V, const int* __restrict__ mask,
                 float* __restrict__ Y)
{
    extern __shared__ __align__(16) float sm[];
    float (*Qs)[64] = (float(*)[64])sm;                       // 4096 floats
    float (*KP)[68] = (float(*)[68])(sm + 4096);              // 4352 floats
    float (*Vs)[64] = (float(*)[64])(sm + 4096 + 4352);       // 4096 floats
    int*   mk       = (int*)(sm + 4096 + 4352 + 4096);        // 64 ints

    const int t    = threadIdx.x;
    const int tx   = t & 15;
    const int ty   = t >> 4;
    const int q0   = blockIdx.x * 64;
    const int bh   = blockIdx.y;
    const int tokb = (bh >> 4) * 2048;
    const int colb = (bh & 15) * 64;

    const int lr  = t >> 4;          // 0..15
    const int ld4 = (t & 15) * 4;    // 0..60

    // load Q tile (transposed, pre-scaled by 1/8)
    #pragma unroll
    for (int x = 0; x < 4; ++x) {
        const int i = lr + x * 16;
        float4 v = *(const float4*)&Q[(size_t)(tokb + q0 + i) * 1024 + colb + ld4];
        Qs[ld4 + 0][i] = v.x * 0.125f;
        Qs[ld4 + 1][i] = v.y * 0.125f;
        Qs[ld4 + 2][i] = v.z * 0.125f;
        Qs[ld4 + 3][i] = v.w * 0.125f;
    }

    float m_i[4], l_i[4], o[4][4];
    #pragma unroll
    for (int i = 0; i < 4; ++i) {
        m_i[i] = -1e30f; l_i[i] = 0.0f;
        #pragma unroll
        for (int j = 0; j < 4; ++j) o[i][j] = 0.0f;
    }

    for (int kv0 = 0; kv0 < 2048; kv0 += 64) {
        __syncthreads();   // protect KP/Vs reuse across iterations
        // load K (transposed) and V (direct) tiles
        #pragma unroll
        for (int x = 0; x < 4; ++x) {
            const int j = lr + x * 16;
            float4 kv = *(const float4*)&K[(size_t)(tokb + kv0 + j) * 1024 + colb + ld4];
            KP[ld4 + 0][j] = kv.x; KP[ld4 + 1][j] = kv.y;
            KP[ld4 + 2][j] = kv.z; KP[ld4 + 3][j] = kv.w;
            float4 vv = *(const float4*)&V[(size_t)(tokb + kv0 + j) * 1024 + colb + ld4];
            *(float4*)&Vs[j][ld4] = vv;
        }
        if (t < 64) mk[t] = mask[tokb + kv0 + t];
        __syncthreads();

        // S tile: 4x4 per thread over d=64
        float s[4][4];
        #pragma unroll
        for (int i = 0; i < 4; ++i)
            #pragma unroll
            for (int j = 0; j < 4; ++j) s[i][j] = 0.0f;

        #pragma unroll 8
        for (int d = 0; d < 64; ++d) {
            float4 q4 = *(const float4*)&Qs[d][ty * 4];
            float4 k4 = *(const float4*)&KP[d][tx * 4];
            float qa[4] = {q4.x, q4.y, q4.z, q4.w};
            float kb[4] = {k4.x, k4.y, k4.z, k4.w};
            #pragma unroll
            for (int i = 0; i < 4; ++i)
                #pragma unroll
                for (int j = 0; j < 4; ++j)
                    s[i][j] = fmaf(qa[i], kb[j], s[i][j]);
        }
        __syncthreads();   // done reading KP as K^T

        // online softmax; write P transposed into KP
        #pragma unroll
        for (int ri = 0; ri < 4; ++ri) {
            float rm = -1e30f;
            #pragma unroll
            for (int ci = 0; ci < 4; ++ci) {
                if (mk[tx * 4 + ci] == 0) s[ri][ci] = -1e30f;
                rm = fmaxf(rm, s[ri][ci]);
            }
            #pragma unroll
            for (int off = 1; off < 16; off <<= 1)
                rm = fmaxf(rm, __shfl_xor_sync(0xffffffffu, rm, off));
            const float mn    = fmaxf(m_i[ri], rm);
            const float alpha = __expf(m_i[ri] - mn);
            float rs = 0.0f;
            float p[4];
            #pragma unroll
            for (int ci = 0; ci < 4; ++ci) {
                p[ci] = __expf(s[ri][ci] - mn);
                rs += p[ci];
            }
            #pragma unroll
            for (int off = 1; off < 16; off <<= 1)
                rs += __shfl_xor_sync(0xffffffffu, rs, off);
            l_i[ri] = l_i[ri] * alpha + rs;
            m_i[ri] = mn;
            #pragma unroll
            for (int ci = 0; ci < 4; ++ci) {
                o[ri][ci] *= alpha;
                KP[tx * 4 + ci][ty * 4 + ri] = p[ci];   // P^T
            }
        }
        __syncthreads();

        // O += P @ V  (4x4 per thread over j=64)
        #pragma unroll 8
        for (int j = 0; j < 64; ++j) {
            float4 p4 = *(const float4*)&KP[j][ty * 4];
            float4 v4 = *(const float4*)&Vs[j][tx * 4];
            float pa[4] = {p4.x, p4.y, p4.z, p4.w};
            float vb[4] = {v4.x, v4.y, v4.z, v4.w};
            #pragma unroll
            for (int i = 0; i < 4; ++i)
                #pragma unroll
                for (int c = 0; c < 4; ++c)
                    o[i][c] = fmaf(pa[i], vb[c], o[i][c]);
        }
    }

    #pragma unroll
    for (int ri = 0; ri < 4; ++ri) {
        const float inv = 1.0f / l_i[ri];
        float4 r;
        r.x = o[ri][0] * inv; r.y = o[ri][1] * inv;
        r.z = o[ri][2] * inv; r.w = o[ri][3] * inv;
        *(float4*)&Y[(size_t)(tokb + q0 + ty * 4 + ri) * 1024 + colb + tx * 4] = r;
    }
}

// ---------------------------------------------------------------------------
// LayerNorm: one row (1024) per CTA, 256 threads, biased variance, eps=1e-5
// ---------------------------------------------------------------------------
__global__ __launch_bounds__(256)
void ln_kernel(const float* __restrict__ X, const float* __restrict__ w,
               const float* __restrict__ b, float* __restrict__ out)
{
    __shared__ float red[2][8];
    const int t = threadIdx.x;
    const size_t row = blockIdx.x;
    float4 xv = *(const float4*)&X[row * 1024 + t * 4];
    float s  = xv.x + xv.y + xv.z + xv.w;
    float s2 = xv.x * xv.x + xv.y * xv.y + xv.z * xv.z + xv.w * xv.w;
    #pragma unroll
    for (int off = 16; off; off >>= 1) {
        s  += __shfl_xor_sync(0xffffffffu, s,  off);
        s2 += __shfl_xor_sync(0xffffffffu, s2, off);
    }
    if ((t & 31) == 0) { red[0][t >> 5] = s; red[1][t >> 5] = s2; }
    __syncthreads();
    float S = 0.0f, S2 = 0.0f;
    #pragma unroll
    for (int i = 0; i < 8; ++i) { S += red[0][i]; S2 += red[1][i]; }
    const float mean = S * (1.0f / 1024.0f);
    const float var  = S2 * (1.0f / 1024.0f) - mean * mean;
    const float rstd = rsqrtf(var + 1e-5f);
    float4 wv = *(const float4*)&w[t * 4];
    float4 bv = *(const float4*)&b[t * 4];
    float4 r;
    r.x = (xv.x - mean) * rstd * wv.x + bv.x;
    r.y = (xv.y - mean) * rstd * wv.y + bv.y;
    r.z = (xv.z - mean) * rstd * wv.z + bv.z;
    r.w = (xv.w - mean) * rstd * wv.w + bv.w;
    *(float4*)&out[row * 1024 + t * 4] = r;
}

// ---------------------------------------------------------------------------
// launch
// ---------------------------------------------------------------------------
extern "C" void kernel_launch(void* const* d_in, const int* in_sizes, int n_in,
                              void* d_out, int out_size)
{
    (void)in_sizes; (void)n_in; (void)out_size;
    const float* x    = (const float*)d_in[0];
    const int*   mask = (const int*)  d_in[1];
    const float* WQ   = (const float*)d_in[2];
    const float* bQ   = (const float*)d_in[3];
    const float* WK   = (const float*)d_in[4];
    const float* bK   = (const float*)d_in[5];
    const float* WV   = (const float*)d_in[6];
    const float* bV   = (const float*)d_in[7];
    const float* WY   = (const float*)d_in[8];
    const float* bY   = (const float*)d_in[9];
    const float* ln1w = (const float*)d_in[10];
    const float* ln1b = (const float*)d_in[11];
    const float* ln2w = (const float*)d_in[12];
    const float* ln2b = (const float*)d_in[13];
    const float* W1   = (const float*)d_in[14];
    const float* b1   = (const float*)d_in[15];
    const float* W2   = (const float*)d_in[16];
    const float* b2   = (const float*)d_in[17];
    float* out = (float*)d_out;

    float *Qp, *Kp, *Vp, *Yp, *FFp;
    cudaGetSymbolAddress((void**)&Qp,  g_Q);
    cudaGetSymbolAddress((void**)&Kp,  g_K);
    cudaGetSymbolAddress((void**)&Vp,  g_V);
    cudaGetSymbolAddress((void**)&Yp,  g_Y);
    cudaGetSymbolAddress((void**)&FFp, g_FF);

    const int ATTN_SMEM = (4096 + 4352 + 4096 + 64) * 4;  // 50432 bytes
    cudaFuncSetAttribute(attn_kernel,
                         cudaFuncAttributeMaxDynamicSharedMemorySize, ATTN_SMEM);

    dim3 blk(256);
    dim3 gP(8, 32);    // N=1024, M=4096
    dim3 gF(32, 32);   // N=4096, M=4096

    // QKV projections
    sgemm_kernel<0><<<gP, blk>>>(x, WQ, bQ, nullptr, Qp, 4096, 1024, 1024);
    sgemm_kernel<0><<<gP, blk>>>(x, WK, bK, nullptr, Kp, 4096, 1024, 1024);
    sgemm_kernel<0><<<gP, blk>>>(x, WV, bV, nullptr, Vp, 4096, 1024, 1024);

    // attention -> g_Y
    attn_kernel<<<dim3(32, 32), blk, ATTN_SMEM>>>(Qp, Kp, Vp, mask, Yp);

    // a + x = y@WY + bY + x   -> g_Q (Q no longer needed)
    sgemm_kernel<2><<<gP, blk>>>(Yp, WY, bY, x, Qp, 4096, 1024, 1024);

    // h = LN1(a + x)          -> g_K
    ln_kernel<<<4096, blk>>>(Qp, ln1w, ln1b, Kp);

    // gelu(h@W1 + b1)         -> g_FF
    sgemm_kernel<1><<<gF, blk>>>(Kp, W1, b1, nullptr, FFp, 4096, 4096, 1024);

    // ff@W2 + b2 + h          -> g_V
    sgemm_kernel<2><<<gP, blk>>>(FFp, W2, b2, Kp, Vp, 4096, 1024, 4096);

    // out = LN2(ff + h)       -> d_out
    ln_kernel<<<4096, blk>>>(Vp, ln2w, ln2b, out);
}